// round 16
// baseline (speedup 1.0000x reference)
#include <cuda_runtime.h>
#include <cuda_fp16.h>
#include <math.h>

#define NNODES 100000
#define EDGES  3200000
#define HDIM   128
#define EDIM   16
#define PTYPES 6
#define CAP    96       // bucket slots per row; Poisson(32) max-degree ~65
#define CONVB  1024     // blocks doing fp16 conversion in k_work

// ---- __device__ scratch (allocations are banned) ----
__device__ int    g_cnt[NNODES];          // per-row cursor (zeroed each launch)
__device__ int    g_bkt[NNODES * CAP];    // packed (col | ptype<<24), 38.4 MB
__device__ int    g_ovf;                  // spill count
__device__ int    g_sp_row[EDGES];        // spill rows (adversarial inputs only)
__device__ int    g_sp_pk[EDGES];         // spill packed entries
__device__ __half g_kh[NNODES * HDIM];    // fp16 k     (25.6 MB)
__device__ __half g_vh[NNODES * HDIM];    // fp16 v     (25.6 MB)
__device__ __half g_eh[NNODES * EDIM];    // fp16 eigs   (3.2 MB)
__device__ float  g_pexp[PTYPES];
__device__ float  g_expl;

// ---------------------------------------------------------------------------
// 0) zero: cursors + spill counter + exp tables (must precede scatter atomics)
// ---------------------------------------------------------------------------
__global__ void k_zero(const float* __restrict__ lambda0,
                       const float* __restrict__ path_w, int n_nodes) {
    int tid = blockIdx.x * blockDim.x + threadIdx.x;
    int stride = gridDim.x * blockDim.x;
    for (int i = tid; i < n_nodes; i += stride) g_cnt[i] = 0;
    if (tid < PTYPES) g_pexp[tid] = expf(path_w[tid]);
    if (tid == 0) { g_expl = expf(lambda0[0]); g_ovf = 0; }
}

// ---------------------------------------------------------------------------
// 1) block-specialized work kernel (R15, measured):
//    blocks [0, CONVB)        : fp32 -> fp16 conversion (DRAM-streaming)
//    blocks [CONVB, CONVB+eb8): bucket scatter (atomic/latency)
// ---------------------------------------------------------------------------
__device__ __forceinline__ void bkt_put(int row, int pk) {
    int pos = atomicAdd(&g_cnt[row], 1);
    if (pos < CAP) {
        __stcs(&g_bkt[row * CAP + pos], pk);
    } else {                          // adversarial-degree spill
        int s = atomicAdd(&g_ovf, 1);
        g_sp_row[s] = row;
        g_sp_pk[s]  = pk;
    }
}

__global__ void k_work(const float* __restrict__ k,
                       const float* __restrict__ v,
                       const float* __restrict__ eigs,
                       const int*   __restrict__ indices,
                       const int*   __restrict__ ptype,
                       int n_nodes, int n_edges) {
    if (blockIdx.x < CONVB) {
        int tid = blockIdx.x * blockDim.x + threadIdx.x;
        int stride = CONVB * blockDim.x;
        int nk4 = n_nodes * (HDIM / 4);
        for (int i = tid; i < nk4; i += stride) {
            float4 f = __ldcs(reinterpret_cast<const float4*>(k) + i);
            __half2 lo = __floats2half2_rn(f.x, f.y);
            __half2 hi = __floats2half2_rn(f.z, f.w);
            uint2 o;
            o.x = *reinterpret_cast<unsigned*>(&lo);
            o.y = *reinterpret_cast<unsigned*>(&hi);
            reinterpret_cast<uint2*>(g_kh)[i] = o;
        }
        for (int i = tid; i < nk4; i += stride) {
            float4 f = __ldcs(reinterpret_cast<const float4*>(v) + i);
            __half2 lo = __floats2half2_rn(f.x, f.y);
            __half2 hi = __floats2half2_rn(f.z, f.w);
            uint2 o;
            o.x = *reinterpret_cast<unsigned*>(&lo);
            o.y = *reinterpret_cast<unsigned*>(&hi);
            reinterpret_cast<uint2*>(g_vh)[i] = o;
        }
        int ne4 = n_nodes * (EDIM / 4);
        for (int i = tid; i < ne4; i += stride) {
            float4 f = __ldcs(reinterpret_cast<const float4*>(eigs) + i);
            __half2 lo = __floats2half2_rn(f.x, f.y);
            __half2 hi = __floats2half2_rn(f.z, f.w);
            uint2 o;
            o.x = *reinterpret_cast<unsigned*>(&lo);
            o.y = *reinterpret_cast<unsigned*>(&hi);
            reinterpret_cast<uint2*>(g_eh)[i] = o;
        }
    } else {
        int t = (blockIdx.x - CONVB) * blockDim.x + threadIdx.x;
        int base = t * 8;
        if (base + 8 <= n_edges) {
            int4 r0 = __ldcs(reinterpret_cast<const int4*>(indices) + t * 2);
            int4 r1 = __ldcs(reinterpret_cast<const int4*>(indices) + t * 2 + 1);
            int4 c0 = __ldcs(reinterpret_cast<const int4*>(indices + n_edges) + t * 2);
            int4 c1 = __ldcs(reinterpret_cast<const int4*>(indices + n_edges) + t * 2 + 1);
            int4 p0 = __ldcs(reinterpret_cast<const int4*>(ptype) + t * 2);
            int4 p1 = __ldcs(reinterpret_cast<const int4*>(ptype) + t * 2 + 1);
            bkt_put(r0.x, c0.x | (p0.x << 24));
            bkt_put(r0.y, c0.y | (p0.y << 24));
            bkt_put(r0.z, c0.z | (p0.z << 24));
            bkt_put(r0.w, c0.w | (p0.w << 24));
            bkt_put(r1.x, c1.x | (p1.x << 24));
            bkt_put(r1.y, c1.y | (p1.y << 24));
            bkt_put(r1.z, c1.z | (p1.z << 24));
            bkt_put(r1.w, c1.w | (p1.w << 24));
        } else if (base < n_edges) {
            for (int e = base; e < n_edges; e++) {
                int row = __ldg(indices + e);
                int col = __ldg(indices + n_edges + e);
                int pt  = __ldg(ptype + e);
                bkt_put(row, col | (pt << 24));
            }
        }
    }
}

// ---------------------------------------------------------------------------
// 2) fused: warp per row, half-warp per edge, uniform predicated 4-edge loop
//    with the NEXT iteration's packed indices prefetched (index-load latency
//    removed from the dependent index->gather chain).
// ---------------------------------------------------------------------------
__device__ __forceinline__ float dot8h(float4 qa, float4 qb, uint4 kr) {
    float2 k0 = __half22float2(*reinterpret_cast<__half2*>(&kr.x));
    float2 k1 = __half22float2(*reinterpret_cast<__half2*>(&kr.y));
    float2 k2 = __half22float2(*reinterpret_cast<__half2*>(&kr.z));
    float2 k3 = __half22float2(*reinterpret_cast<__half2*>(&kr.w));
    return qa.x * k0.x + qa.y * k0.y + qa.z * k1.x + qa.w * k1.y
         + qb.x * k2.x + qb.y * k2.y + qb.z * k3.x + qb.w * k3.y;
}

__global__ void __launch_bounds__(256)
k_fused(const float* __restrict__ q, float* __restrict__ out, int n_nodes) {
    __shared__ float s_pexp[PTYPES];
    if (threadIdx.x < PTYPES) s_pexp[threadIdx.x] = g_pexp[threadIdx.x];
    __syncthreads();

    int warp = (blockIdx.x * blockDim.x + threadIdx.x) >> 5;
    int lane = threadIdx.x & 31;
    if (warp >= n_nodes) return;
    const int row  = warp;
    const int half = lane >> 4;
    const int hl   = lane & 15;
    const int cnt = g_cnt[row];
    const int deg = cnt < CAP ? cnt : CAP;
    const int beg = row * CAP;
    const int end = beg + deg;
    const int ovf = g_ovf;            // 0 for the bench input

    float acc0[8] = {0,0,0,0,0,0,0,0};
    float acc1[8] = {0,0,0,0,0,0,0,0};
    float d0 = 0.f, d1 = 0.f;
    float res[8];

    if (deg > 0 || ovf > 0) {
        const float inv_sqrt_h = 0.08838834764831845f;  // 1/sqrt(128)
        const float* qrow = q + (size_t)row * HDIM + hl * 8;
        float4 qa = __ldcs(reinterpret_cast<const float4*>(qrow));
        float4 qb = __ldcs(reinterpret_cast<const float4*>(qrow) + 1);
        qa.x *= inv_sqrt_h; qa.y *= inv_sqrt_h; qa.z *= inv_sqrt_h; qa.w *= inv_sqrt_h;
        qb.x *= inv_sqrt_h; qb.y *= inv_sqrt_h; qb.z *= inv_sqrt_h; qb.w *= inv_sqrt_h;
        float er = g_expl * __half2float(__ldg(g_eh + (size_t)row * EDIM + hl));

        // ---- uniform 4-edge loop with index prefetch ----
        int iters = (deg + 3) >> 2;
        int jj0 = beg + half;
        int jj1 = beg + 2 + half;
        int pkA = __ldcs(g_bkt + (jj0 < end ? jj0 : beg));
        int pkB = __ldcs(g_bkt + (jj1 < end ? jj1 : beg));

        for (int it = 0; it < iters; it++) {
            int base = beg + (it << 2);
            int e0i = base + half;
            int e1i = base + 2 + half;
            bool va = e0i < end;
            bool vb = e1i < end;
            int pk0 = pkA;
            int pk1 = pkB;
            // prefetch next iteration's indices (clamped; consumed or discarded)
            int n0 = base + 4 + half;
            int n1 = base + 6 + half;
            pkA = __ldcs(g_bkt + (n0 < end ? n0 : beg));
            pkB = __ldcs(g_bkt + (n1 < end ? n1 : beg));

            int c0 = pk0 & 0xFFFFFF, c1 = pk1 & 0xFFFFFF;
            uint4 kr0 = __ldg(reinterpret_cast<const uint4*>(g_kh + (size_t)c0 * HDIM + hl * 8));
            uint4 kr1 = __ldg(reinterpret_cast<const uint4*>(g_kh + (size_t)c1 * HDIM + hl * 8));
            uint4 vr0 = __ldg(reinterpret_cast<const uint4*>(g_vh + (size_t)c0 * HDIM + hl * 8));
            uint4 vr1 = __ldg(reinterpret_cast<const uint4*>(g_vh + (size_t)c1 * HDIM + hl * 8));
            float ec0 = __half2float(__ldg(g_eh + (size_t)c0 * EDIM + hl));
            float ec1 = __half2float(__ldg(g_eh + (size_t)c1 * EDIM + hl));

            float z0 = dot8h(qa, qb, kr0) + er * ec0;
            float z1 = dot8h(qa, qb, kr1) + er * ec1;
            #pragma unroll
            for (int o = 8; o > 0; o >>= 1) {
                z0 += __shfl_xor_sync(0xffffffffu, z0, o);
                z1 += __shfl_xor_sync(0xffffffffu, z1, o);
            }
            float e00 = va ? __expf(z0) : 0.f;
            float e01 = vb ? __expf(z1) : 0.f;
            float pw0 = va ? s_pexp[((unsigned)pk0) >> 24] : 0.f;
            float pw1 = vb ? s_pexp[((unsigned)pk1) >> 24] : 0.f;
            d0 += e00 + e01;
            d1 += pw0 + pw1;

            float2 v0[4], v1[4];
            v0[0] = __half22float2(*reinterpret_cast<__half2*>(&vr0.x));
            v0[1] = __half22float2(*reinterpret_cast<__half2*>(&vr0.y));
            v0[2] = __half22float2(*reinterpret_cast<__half2*>(&vr0.z));
            v0[3] = __half22float2(*reinterpret_cast<__half2*>(&vr0.w));
            v1[0] = __half22float2(*reinterpret_cast<__half2*>(&vr1.x));
            v1[1] = __half22float2(*reinterpret_cast<__half2*>(&vr1.y));
            v1[2] = __half22float2(*reinterpret_cast<__half2*>(&vr1.z));
            v1[3] = __half22float2(*reinterpret_cast<__half2*>(&vr1.w));
            #pragma unroll
            for (int i = 0; i < 4; i++) {
                acc0[2*i]   += e00 * v0[i].x + e01 * v1[i].x;
                acc0[2*i+1] += e00 * v0[i].y + e01 * v1[i].y;
                acc1[2*i]   += pw0 * v0[i].x + pw1 * v1[i].x;
                acc1[2*i+1] += pw0 * v0[i].y + pw1 * v1[i].y;
            }
        }

        // spill entries (only when a row exceeded CAP; never for bench input)
        for (int s = 0; s < ovf; s++) {
            if (g_sp_row[s] != row) continue;
            int pk0 = g_sp_pk[s];
            int c0 = pk0 & 0xFFFFFF;
            uint4 kr0 = __ldg(reinterpret_cast<const uint4*>(g_kh + (size_t)c0 * HDIM + hl * 8));
            uint4 vr0 = __ldg(reinterpret_cast<const uint4*>(g_vh + (size_t)c0 * HDIM + hl * 8));
            float ec0 = __half2float(__ldg(g_eh + (size_t)c0 * EDIM + hl));
            float z0 = dot8h(qa, qb, kr0) + er * ec0;
            #pragma unroll
            for (int o = 8; o > 0; o >>= 1)
                z0 += __shfl_xor_sync(0xffffffffu, z0, o);
            bool act = (half == 0);          // count each spill edge once
            float e00 = act ? __expf(z0) : 0.f;
            float pw0 = act ? s_pexp[((unsigned)pk0) >> 24] : 0.f;
            d0 += e00;
            d1 += pw0;
            float2 v0[4];
            v0[0] = __half22float2(*reinterpret_cast<__half2*>(&vr0.x));
            v0[1] = __half22float2(*reinterpret_cast<__half2*>(&vr0.y));
            v0[2] = __half22float2(*reinterpret_cast<__half2*>(&vr0.z));
            v0[3] = __half22float2(*reinterpret_cast<__half2*>(&vr0.w));
            #pragma unroll
            for (int i = 0; i < 4; i++) {
                acc0[2*i]   += e00 * v0[i].x;
                acc0[2*i+1] += e00 * v0[i].y;
                acc1[2*i]   += pw0 * v0[i].x;
                acc1[2*i+1] += pw0 * v0[i].y;
            }
        }

        // combine halves and normalize
        d0 += __shfl_xor_sync(0xffffffffu, d0, 16);
        d1 += __shfl_xor_sync(0xffffffffu, d1, 16);
        float i0 = (d0 != 0.f) ? 0.5f / d0 : 0.f;
        float i1 = (d1 != 0.f) ? 0.5f / d1 : 0.f;
        #pragma unroll
        for (int i = 0; i < 8; i++) {
            acc0[i] += __shfl_xor_sync(0xffffffffu, acc0[i], 16);
            acc1[i] += __shfl_xor_sync(0xffffffffu, acc1[i], 16);
            res[i] = i0 * acc0[i] + i1 * acc1[i];
        }
    } else {
        #pragma unroll
        for (int i = 0; i < 8; i++) res[i] = 0.f;
    }

    if (half == 0) {
        float4* o = reinterpret_cast<float4*>(out + (size_t)row * HDIM + hl * 8);
        __stcs(o,     make_float4(res[0], res[1], res[2], res[3]));
        __stcs(o + 1, make_float4(res[4], res[5], res[6], res[7]));
    }
}

// ---------------------------------------------------------------------------
extern "C" void kernel_launch(void* const* d_in, const int* in_sizes, int n_in,
                              void* d_out, int out_size) {
    const float* q       = (const float*)d_in[0];
    const float* k       = (const float*)d_in[1];
    const float* v       = (const float*)d_in[2];
    const float* eigs    = (const float*)d_in[3];
    const float* lambda0 = (const float*)d_in[4];
    const float* path_w  = (const float*)d_in[5];
    const int*   indices = (const int*)d_in[6];
    const int*   ptype   = (const int*)d_in[7];
    float*       out     = (float*)d_out;

    int n_edges = in_sizes[6] / 2;
    int n_nodes = in_sizes[0] / HDIM;
    if (n_edges > EDGES)  n_edges = EDGES;
    if (n_nodes > NNODES) n_nodes = NNODES;

    int eb8 = (n_edges / 8 + 255) / 256 + 1;   // scatter blocks
    int rb  = (n_nodes * 32 + 255) / 256;

    k_zero<<<512, 256>>>(lambda0, path_w, n_nodes);
    k_work<<<CONVB + eb8, 256>>>(k, v, eigs, indices, ptype, n_nodes, n_edges);
    k_fused<<<rb, 256>>>(q, out, n_nodes);
}